// round 5
// baseline (speedup 1.0000x reference)
#include <cuda_runtime.h>
#include <cstdint>
#include <cstddef>
#include <cmath>

// Problem constants
#define T_STEPS 1000
#define BATCH   64
#define NDIM    512
#define KDIM    512
#define MROWS   (BATCH * T_STEPS)   // 64000

static constexpr size_t PLANE      = (size_t)BATCH * NDIM;          // 32768
static constexpr size_t STATES_OFF = (size_t)T_STEPS * PLANE;       // outputs plane elems
static constexpr size_t DEC_OFF    = STATES_OFF + 3 * STATES_OFF;   // after states [T,3,B,N]

// Scratch
__device__ __align__(16) float g_I[(size_t)MROWS * NDIM];
__device__ float g_r[T_STEPS * BATCH];

// ---------------------------------------------------------------------------
// tf32 helpers (sm_80+ compatible)
// ---------------------------------------------------------------------------
__device__ __forceinline__ uint32_t tf32_rna_bits(float x) {
    uint32_t u;
    asm("cvt.rna.tf32.f32 %0, %1;" : "=r"(u) : "f"(x));
    return u;
}

__device__ __forceinline__ void mma_tf32(float* c, const uint32_t* a, const uint32_t* b) {
    asm volatile(
        "mma.sync.aligned.m16n8k8.row.col.f32.tf32.tf32.f32 "
        "{%0,%1,%2,%3}, {%4,%5,%6,%7}, {%8,%9}, {%0,%1,%2,%3};\n"
        : "+f"(c[0]), "+f"(c[1]), "+f"(c[2]), "+f"(c[3])
        : "r"(a[0]), "r"(a[1]), "r"(a[2]), "r"(a[3]), "r"(b[0]), "r"(b[1]));
}

// ---------------------------------------------------------------------------
// Kernel 1: I = X @ W1^T  (NT GEMM), mma.sync tf32, 3-product split.
// CTA 128x128, BK=16, 8 warps (4x2), warp tile 32x64.
// smem: hi/lo interleaved float2 planes, row stride 20 float2.
//   tile = 128*20 f2 = 20KB; stage = A+B = 40KB; 2 stages = 80KB -> 2 CTAs/SM.
// Producer: LDG float4 -> register split -> STS.128 (h0,l0,h1,l1).
// Consumer: LDS.64 per element (hi+lo in one load), zero cvt in hot loop.
// ---------------------------------------------------------------------------
#define BK      16
#define NCHUNK  (KDIM / BK)        // 32
#define STR2    20                 // float2 per row (16 + 4 pad)
#define TILE2   (128 * STR2)       // 2560 f2 per tile
#define STAGE2  (2 * TILE2)        // 5120 f2 per stage (A + B)

struct LdgRegs { float4 a[2]; float4 b[2]; };

__device__ __forceinline__ void ldg_chunk(LdgRegs& r, const float* __restrict__ xptr,
                                          const float* __restrict__ wptr, int ck)
{
    const float4* xa = (const float4*)(xptr + ck * BK);
    const float4* wa = (const float4*)(wptr + ck * BK);
    r.a[0] = xa[0]; r.a[1] = xa[1];
    r.b[0] = wa[0]; r.b[1] = wa[1];
}

__device__ __forceinline__ void split_sts(float2* dst, float4 v)
{
    // dst points at f2 index (even) -> write 2x STS.128 of (h,l,h,l)
    float4 w0, w1;
    w0.x = __uint_as_float(tf32_rna_bits(v.x)); w0.y = __uint_as_float(tf32_rna_bits(v.x - w0.x));
    w0.z = __uint_as_float(tf32_rna_bits(v.y)); w0.w = __uint_as_float(tf32_rna_bits(v.y - w0.z));
    w1.x = __uint_as_float(tf32_rna_bits(v.z)); w1.y = __uint_as_float(tf32_rna_bits(v.z - w1.x));
    w1.z = __uint_as_float(tf32_rna_bits(v.w)); w1.w = __uint_as_float(tf32_rna_bits(v.w - w1.z));
    ((float4*)dst)[0] = w0;
    ((float4*)dst)[1] = w1;
}

__device__ __forceinline__ void sts_chunk(float2* stage, const LdgRegs& r, int row, int kb)
{
    float2* sA = stage + row * STR2 + kb;
    float2* sB = sA + TILE2;
    split_sts(sA,     r.a[0]);
    split_sts(sA + 4, r.a[1]);
    split_sts(sB,     r.b[0]);
    split_sts(sB + 4, r.b[1]);
}

__device__ __forceinline__ void compute_chunk(const float2* __restrict__ stage,
                                              float (&acc)[2][8][4],
                                              int wm, int wn, int lane)
{
    const float2* sA = stage;
    const float2* sB = stage + TILE2;
    const int lq = lane >> 2;        // 0..7
    const int lr = lane & 3;         // 0..3

    #pragma unroll
    for (int kk = 0; kk < BK; kk += 8) {
        const int c0 = kk + lr;
        uint32_t Ah[2][4], Al[2][4];
        #pragma unroll
        for (int mt = 0; mt < 2; mt++) {
            const int r0 = wm * 32 + mt * 16 + lq;
            float2 a0 = sA[r0 * STR2 + c0];
            float2 a1 = sA[(r0 + 8) * STR2 + c0];
            float2 a2 = sA[r0 * STR2 + c0 + 4];
            float2 a3 = sA[(r0 + 8) * STR2 + c0 + 4];
            Ah[mt][0] = __float_as_uint(a0.x); Al[mt][0] = __float_as_uint(a0.y);
            Ah[mt][1] = __float_as_uint(a1.x); Al[mt][1] = __float_as_uint(a1.y);
            Ah[mt][2] = __float_as_uint(a2.x); Al[mt][2] = __float_as_uint(a2.y);
            Ah[mt][3] = __float_as_uint(a3.x); Al[mt][3] = __float_as_uint(a3.y);
        }
        // B in two groups of 4 nt to bound live registers
        #pragma unroll
        for (int g = 0; g < 2; g++) {
            uint32_t Bh[4][2], Bl[4][2];
            #pragma unroll
            for (int nt = 0; nt < 4; nt++) {
                const int nr = wn * 64 + (g * 4 + nt) * 8 + lq;
                float2 b0 = sB[nr * STR2 + c0];
                float2 b1 = sB[nr * STR2 + c0 + 4];
                Bh[nt][0] = __float_as_uint(b0.x); Bl[nt][0] = __float_as_uint(b0.y);
                Bh[nt][1] = __float_as_uint(b1.x); Bl[nt][1] = __float_as_uint(b1.y);
            }
            #pragma unroll
            for (int mt = 0; mt < 2; mt++)
                #pragma unroll
                for (int nt = 0; nt < 4; nt++) {
                    float* a = acc[mt][g * 4 + nt];
                    mma_tf32(a, Ah[mt], Bh[nt]);
                    mma_tf32(a, Ah[mt], Bl[nt]);
                    mma_tf32(a, Al[mt], Bh[nt]);
                }
        }
    }
}

__global__ __launch_bounds__(256, 2) void gemm_tf32_kernel(const float* __restrict__ X,
                                                           const float* __restrict__ W)
{
    extern __shared__ float2 smem2[];        // 2 stages * 5120 f2 = 80KB
    const int tid  = threadIdx.x;
    const int wid  = tid >> 5;
    const int lane = tid & 31;
    const int wm   = wid & 3;                // 0..3
    const int wn   = wid >> 2;               // 0..1
    // bn fastest: the 4 CTAs sharing an X tile run adjacently -> X hits L2
    const int bn   = blockIdx.x * 128;
    const int bm   = blockIdx.y * 128;

    // loader mapping: row = tid>>1 (0..127), kb = (tid&1)*8
    const int lrow = tid >> 1;
    const int lkb  = (tid & 1) * 8;
    const float* xptr = X + (size_t)(bm + lrow) * KDIM + lkb;
    const float* wptr = W + (size_t)(bn + lrow) * KDIM + lkb;

    float acc[2][8][4];
    #pragma unroll
    for (int mt = 0; mt < 2; mt++)
        #pragma unroll
        for (int nt = 0; nt < 8; nt++)
            #pragma unroll
            for (int j = 0; j < 4; j++) acc[mt][nt][j] = 0.f;

    {
        LdgRegs r0;
        ldg_chunk(r0, xptr, wptr, 0);
        sts_chunk(smem2, r0, lrow, lkb);
    }
    __syncthreads();

    #pragma unroll 1
    for (int ck = 0; ck < NCHUNK; ck++) {
        const int cur = ck & 1;
        LdgRegs nr;
        if (ck + 1 < NCHUNK) ldg_chunk(nr, xptr, wptr, ck + 1);   // LDG in flight
        compute_chunk(smem2 + cur * STAGE2, acc, wm, wn, lane);
        if (ck + 1 < NCHUNK) sts_chunk(smem2 + (cur ^ 1) * STAGE2, nr, lrow, lkb);
        __syncthreads();
    }

    // Epilogue: direct float2 stores
    #pragma unroll
    for (int mt = 0; mt < 2; mt++) {
        const int r0 = bm + wm * 32 + mt * 16 + (lane >> 2);
        #pragma unroll
        for (int nt = 0; nt < 8; nt++) {
            const int c = bn + wn * 64 + nt * 8 + 2 * (lane & 3);
            *(float2*)(g_I + (size_t)r0 * NDIM + c)       = make_float2(acc[mt][nt][0], acc[mt][nt][1]);
            *(float2*)(g_I + (size_t)(r0 + 8) * NDIM + c) = make_float2(acc[mt][nt][2], acc[mt][nt][3]);
        }
    }
}

// ---------------------------------------------------------------------------
// Kernel 2: per-neuron Izhikevich scan. Incremental pointers, streaming stores.
// ---------------------------------------------------------------------------
struct NeuronP { float TS, V2, V1, V0, KA, Bp, TH, Cc, D; };

__device__ __forceinline__ void snn_step(float Ic, const NeuronP& P,
                                         float& u, float& v,
                                         float*& po, float*& ps)
{
    float t0 = P.V0 - u + Ic;
    t0 = fmaf(P.V1, v, t0);
    t0 = fmaf(P.V2, v * v, t0);
    const float vn = fmaf(P.TS, t0, v);
    const float un = fmaf(P.KA, fmaf(P.Bp, v, -u), u);
    const bool  sp = (vn - P.TH) > 0.f;
    const float s  = sp ? 1.f : 0.f;
    const float vo = sp ? P.Cc : vn;
    const float uo = sp ? (un + P.D) : un;

    *po = s;                      // outputs plane (re-read by reduce)
    __stcs(ps,             uo);   // states planes: write-only -> streaming
    __stcs(ps + PLANE,     vo);
    __stcs(ps + 2 * PLANE, s);
    po += PLANE;
    ps += 3 * PLANE;
    u = uo; v = vo;
}

__global__ __launch_bounds__(128) void scan_kernel(
    const float* __restrict__ st,
    const float* __restrict__ pa,  const float* __restrict__ pb,
    const float* __restrict__ pc,  const float* __restrict__ pd,
    const float* __restrict__ pv2, const float* __restrict__ pv1,
    const float* __restrict__ pv0, const float* __restrict__ ptau,
    const float* __restrict__ pth, const float* __restrict__ pts,
    float* __restrict__ out)
{
    const int g = blockIdx.x * 128 + threadIdx.x;
    const int n = g & (NDIM - 1);

    NeuronP P;
    P.TS = pts[n];
    P.V2 = pv2[n]; P.V1 = pv1[n]; P.V0 = pv0[n];
    P.KA = P.TS / ptau[n] * pa[n];
    P.Bp = pb[n]; P.TH = pth[n]; P.Cc = pc[n]; P.D = pd[n];

    float u = st[g];
    float v = st[PLANE + g];

    const float* Ip = g_I + (size_t)(g >> 9) * ((size_t)T_STEPS * NDIM) + n;
    float* po = out + g;
    float* ps = out + STATES_OFF + g;

    float bufA[8], bufB[8];
    #pragma unroll
    for (int p = 0; p < 8; p++) bufA[p] = __ldcs(Ip + (size_t)p * NDIM);

    #pragma unroll 1
    for (int t0 = 0; t0 < 992; t0 += 16) {
        #pragma unroll
        for (int p = 0; p < 8; p++) bufB[p] = __ldcs(Ip + (size_t)(8 + p) * NDIM);
        #pragma unroll
        for (int p = 0; p < 8; p++) snn_step(bufA[p], P, u, v, po, ps);
        #pragma unroll
        for (int p = 0; p < 8; p++) bufA[p] = __ldcs(Ip + (size_t)(16 + p) * NDIM);
        #pragma unroll
        for (int p = 0; p < 8; p++) snn_step(bufB[p], P, u, v, po, ps);
        Ip += 16 * NDIM;
    }
    #pragma unroll
    for (int p = 0; p < 8; p++) snn_step(bufA[p], P, u, v, po, ps);
}

// ---------------------------------------------------------------------------
// Kernel 3: r[t*B+b] = sum_n s[t,b,n] * W2[n]   (float4 loads)
// ---------------------------------------------------------------------------
__global__ __launch_bounds__(128) void readout_reduce_kernel(
    const float* __restrict__ out, const float* __restrict__ W2)
{
    const int tb  = blockIdx.x;
    const int tid = threadIdx.x;
    const float4 sv = ((const float4*)(out + (size_t)tb * NDIM))[tid];
    const float4 wv = ((const float4*)W2)[tid];

    float sum = fmaf(sv.x, wv.x, fmaf(sv.y, wv.y, fmaf(sv.z, wv.z, sv.w * wv.w)));
    #pragma unroll
    for (int o = 16; o > 0; o >>= 1)
        sum += __shfl_xor_sync(0xffffffffu, sum, o);

    __shared__ float ws[4];
    if ((tid & 31) == 0) ws[tid >> 5] = sum;
    __syncthreads();
    if (tid == 0) g_r[tb] = (ws[0] + ws[1]) + (ws[2] + ws[3]);
}

// ---------------------------------------------------------------------------
// Kernel 4: li recurrence — warp-parallel linear-recurrence scan, 1 warp per b.
// ---------------------------------------------------------------------------
__global__ void li_kernel(const float* __restrict__ stLI,
                          const float* __restrict__ leak,
                          float* __restrict__ out)
{
    const int b = blockIdx.x;
    const int lane = threadIdx.x;    // 32 threads
    const float lk = leak[0];
    const float l1 = lk, l2 = l1 * l1, l4 = l2 * l2, l8 = l4 * l4, l16 = l8 * l8;
    float lpow = lk;                 // leak^(lane+1)
    {
        float sq[5] = {l1, l2, l4, l8, l16};
        #pragma unroll
        for (int i = 0; i < 5; i++)
            if ((lane >> i) & 1) lpow *= sq[i];
    }

    float carry = stLI[b];
    float x = g_r[lane * BATCH + b];

    #pragma unroll 1
    for (int t0 = 0; t0 < T_STEPS; t0 += 32) {
        const int tn = t0 + 32 + lane;
        const float xn = (tn < T_STEPS) ? g_r[tn * BATCH + b] : 0.f;

        float y = x, up;
        up = __shfl_up_sync(0xffffffffu, y, 1);  if (lane >= 1)  y = fmaf(l1,  up, y);
        up = __shfl_up_sync(0xffffffffu, y, 2);  if (lane >= 2)  y = fmaf(l2,  up, y);
        up = __shfl_up_sync(0xffffffffu, y, 4);  if (lane >= 4)  y = fmaf(l4,  up, y);
        up = __shfl_up_sync(0xffffffffu, y, 8);  if (lane >= 8)  y = fmaf(l8,  up, y);
        up = __shfl_up_sync(0xffffffffu, y, 16); if (lane >= 16) y = fmaf(l16, up, y);

        const float li = fmaf(lpow, carry, y);
        if (t0 + lane < T_STEPS)
            out[DEC_OFF + (size_t)(t0 + lane) * BATCH + b] = li;
        carry = __shfl_sync(0xffffffffu, li, 31);
        x = xn;
    }
}

// ---------------------------------------------------------------------------
extern "C" void kernel_launch(void* const* d_in, const int* in_sizes, int n_in,
                              void* d_out, int out_size)
{
    const float* x    = (const float*)d_in[0];
    const float* st   = (const float*)d_in[1];
    const float* stLI = (const float*)d_in[2];
    const float* W1   = (const float*)d_in[3];
    const float* W2   = (const float*)d_in[4];
    const float* a_   = (const float*)d_in[5];
    const float* b_   = (const float*)d_in[6];
    const float* c_   = (const float*)d_in[7];
    const float* d_   = (const float*)d_in[8];
    const float* v2_  = (const float*)d_in[9];
    const float* v1_  = (const float*)d_in[10];
    const float* v0_  = (const float*)d_in[11];
    const float* tau_ = (const float*)d_in[12];
    const float* th_  = (const float*)d_in[13];
    const float* lk_  = (const float*)d_in[14];
    const float* ts_  = (const float*)d_in[15];
    float* out = (float*)d_out;

    const int smem_bytes = 2 * STAGE2 * (int)sizeof(float2);   // 81920
    cudaFuncSetAttribute(gemm_tf32_kernel,
                         cudaFuncAttributeMaxDynamicSharedMemorySize, smem_bytes);

    dim3 ggrid(NDIM / 128, MROWS / 128);   // (4, 500): bn fastest for X-tile L2 reuse
    gemm_tf32_kernel<<<ggrid, 256, smem_bytes>>>(x, W1);
    scan_kernel<<<(BATCH * NDIM) / 128, 128>>>(st, a_, b_, c_, d_, v2_, v1_,
                                               v0_, tau_, th_, ts_, out);
    readout_reduce_kernel<<<T_STEPS * BATCH, 128>>>(out, W2);
    li_kernel<<<BATCH, 32>>>(stLI, lk_, out);
}

// round 6
// speedup vs baseline: 1.5028x; 1.5028x over previous
#include <cuda_runtime.h>
#include <cuda_fp16.h>
#include <cstdint>
#include <cstddef>
#include <cmath>

// Problem constants
#define T_STEPS 1000
#define BATCH   64
#define NDIM    512
#define KDIM    512
#define MROWS   (BATCH * T_STEPS)   // 64000

static constexpr size_t PLANE      = (size_t)BATCH * NDIM;          // 32768
static constexpr size_t STATES_OFF = (size_t)T_STEPS * PLANE;       // outputs plane elems
static constexpr size_t DEC_OFF    = STATES_OFF + 3 * STATES_OFF;   // after states [T,3,B,N]

// Scratch
__device__ __align__(16) float g_I[(size_t)MROWS * NDIM];
__device__ float g_r[T_STEPS * BATCH];

// ---------------------------------------------------------------------------
// fp16 Dekker-pair helpers (sm_80+ compatible)
// Each f32 x -> half2 word (hi = rn16(x), lo = rn16(x - hi)), hi in low half.
// Interleaved along mma-k: k' = 2k is hi, 2k+1 is lo.
//   pass1: A_il x B_il          -> sum hi*hi + lo*lo
//   pass2: A_il x swap16(B_il)  -> sum hi*lo + lo*hi
// Sum of both = full (hi+lo)*(hi+lo) product, ~2^-22 relative error.
// ---------------------------------------------------------------------------
__device__ __forceinline__ uint32_t pack_hilo(float x) {
    __half h = __float2half_rn(x);
    float r = x - __half2float(h);
    __half2 p = __halves2half2(h, __float2half_rn(r));
    return *reinterpret_cast<uint32_t*>(&p);
}

__device__ __forceinline__ void mma_f16(float* c, const uint32_t* a, const uint32_t* b) {
    asm volatile(
        "mma.sync.aligned.m16n8k16.row.col.f32.f16.f16.f32 "
        "{%0,%1,%2,%3}, {%4,%5,%6,%7}, {%8,%9}, {%0,%1,%2,%3};\n"
        : "+f"(c[0]), "+f"(c[1]), "+f"(c[2]), "+f"(c[3])
        : "r"(a[0]), "r"(a[1]), "r"(a[2]), "r"(a[3]), "r"(b[0]), "r"(b[1]));
}

// ---------------------------------------------------------------------------
// Kernel 1: I = X @ W1^T  (NT GEMM), fp16 Dekker-pair mma, 2 passes.
// R3-exact skeleton: CTA 128x128, BK=32 (16 chunks), 8 warps (4x2),
// warp tile 32x64, register-staged double buffer, stride-36-word smem
// (4*lq + lr covers all 32 banks -> conflict-free LDS.32).
// One uint32 word per (row, real k) = half2(hi, lo).
// Tile = 128*36 words = 18KB; stage = A+B = 36KB; 2 stages = 72KB.
// ---------------------------------------------------------------------------
#define BKR    32
#define NCHUNK (KDIM / BKR)        // 16
#define WSTR   36                  // uint32 words per row (32 data + 4 pad)
#define TILEW  (128 * WSTR)        // words per tile
#define STAGEW (2 * TILEW)         // words per stage (A + B)

struct LdgRegs { float4 a[4]; float4 b[4]; };   // 16 floats of A + 16 of B

__device__ __forceinline__ void ldg_chunk(LdgRegs& r, const float* __restrict__ xptr,
                                          const float* __restrict__ wptr, int ck)
{
    const float4* xa = (const float4*)(xptr + ck * BKR);
    const float4* wa = (const float4*)(wptr + ck * BKR);
    #pragma unroll
    for (int j = 0; j < 4; j++) r.a[j] = xa[j];
    #pragma unroll
    for (int j = 0; j < 4; j++) r.b[j] = wa[j];
}

__device__ __forceinline__ void sts_chunk(uint32_t* stage, const LdgRegs& r, int row, int kb)
{
    uint32_t* sA = stage + row * WSTR + kb;
    uint32_t* sB = sA + TILEW;
    const float* fa = (const float*)r.a;
    const float* fb = (const float*)r.b;
    #pragma unroll
    for (int j = 0; j < 4; j++) {
        uint4 w;
        w.x = pack_hilo(fa[j * 4 + 0]); w.y = pack_hilo(fa[j * 4 + 1]);
        w.z = pack_hilo(fa[j * 4 + 2]); w.w = pack_hilo(fa[j * 4 + 3]);
        ((uint4*)sA)[j] = w;
    }
    #pragma unroll
    for (int j = 0; j < 4; j++) {
        uint4 w;
        w.x = pack_hilo(fb[j * 4 + 0]); w.y = pack_hilo(fb[j * 4 + 1]);
        w.z = pack_hilo(fb[j * 4 + 2]); w.w = pack_hilo(fb[j * 4 + 3]);
        ((uint4*)sB)[j] = w;
    }
}

__device__ __forceinline__ void compute_chunk(const uint32_t* __restrict__ stage,
                                              float (&acc)[2][8][4],
                                              int wm, int wn, int lane)
{
    const uint32_t* sA = stage;
    const uint32_t* sB = stage + TILEW;
    const int lq = lane >> 2;        // 0..7
    const int lr = lane & 3;         // 0..3

    // 4 k16-slices per chunk; each slice = 8 real k (16 interleaved k')
    #pragma unroll
    for (int s = 0; s < 4; s++) {
        const int c0 = s * 8 + lr;
        uint32_t A[2][4];
        #pragma unroll
        for (int mt = 0; mt < 2; mt++) {
            const int r0 = wm * 32 + mt * 16 + lq;
            A[mt][0] = sA[r0 * WSTR + c0];
            A[mt][1] = sA[(r0 + 8) * WSTR + c0];
            A[mt][2] = sA[r0 * WSTR + c0 + 4];
            A[mt][3] = sA[(r0 + 8) * WSTR + c0 + 4];
        }
        uint32_t B[8][2];
        #pragma unroll
        for (int nt = 0; nt < 8; nt++) {
            const int nr = wn * 64 + nt * 8 + lq;
            B[nt][0] = sB[nr * WSTR + c0];
            B[nt][1] = sB[nr * WSTR + c0 + 4];
        }
        #pragma unroll
        for (int nt = 0; nt < 8; nt++) {
            uint32_t bs[2];
            bs[0] = __byte_perm(B[nt][0], 0, 0x1032);   // swap 16-bit halves
            bs[1] = __byte_perm(B[nt][1], 0, 0x1032);
            #pragma unroll
            for (int mt = 0; mt < 2; mt++) {
                mma_f16(acc[mt][nt], A[mt], B[nt]);   // hi*hi + lo*lo
                mma_f16(acc[mt][nt], A[mt], bs);      // hi*lo + lo*hi
            }
        }
    }
}

__global__ __launch_bounds__(256, 1) void gemm_f16pair_kernel(const float* __restrict__ X,
                                                              const float* __restrict__ W)
{
    extern __shared__ uint32_t smemw[];      // 2 stages * 9216 words = 72KB
    const int tid  = threadIdx.x;
    const int wid  = tid >> 5;
    const int lane = tid & 31;
    const int wm   = wid & 3;                // 0..3
    const int wn   = wid >> 2;               // 0..1
    const int bm   = blockIdx.x * 128;       // R3 grid order
    const int bn   = blockIdx.y * 128;

    // loader mapping: row = tid>>1 (0..127), kb = (tid&1)*16 real-k offset
    const int lrow = tid >> 1;
    const int lkb  = (tid & 1) * 16;
    const float* xptr = X + (size_t)(bm + lrow) * KDIM + lkb;
    const float* wptr = W + (size_t)(bn + lrow) * KDIM + lkb;

    float acc[2][8][4];
    #pragma unroll
    for (int mt = 0; mt < 2; mt++)
        #pragma unroll
        for (int nt = 0; nt < 8; nt++)
            #pragma unroll
            for (int j = 0; j < 4; j++) acc[mt][nt][j] = 0.f;

    {
        LdgRegs r0;
        ldg_chunk(r0, xptr, wptr, 0);
        sts_chunk(smemw, r0, lrow, lkb);
    }
    __syncthreads();

    #pragma unroll 1
    for (int ck = 0; ck < NCHUNK; ck++) {
        const int cur = ck & 1;
        LdgRegs nr;
        if (ck < NCHUNK - 1) ldg_chunk(nr, xptr, wptr, ck + 1);   // LDGs in flight
        compute_chunk(smemw + cur * STAGEW, acc, wm, wn, lane);   // overlap with LDG
        if (ck < NCHUNK - 1) sts_chunk(smemw + (cur ^ 1) * STAGEW, nr, lrow, lkb);
        __syncthreads();
    }

    // Epilogue: direct float2 stores to g_I
    #pragma unroll
    for (int mt = 0; mt < 2; mt++) {
        const int r0 = bm + wm * 32 + mt * 16 + (lane >> 2);
        #pragma unroll
        for (int nt = 0; nt < 8; nt++) {
            const int c = bn + wn * 64 + nt * 8 + 2 * (lane & 3);
            *(float2*)(g_I + (size_t)r0 * NDIM + c)       = make_float2(acc[mt][nt][0], acc[mt][nt][1]);
            *(float2*)(g_I + (size_t)(r0 + 8) * NDIM + c) = make_float2(acc[mt][nt][2], acc[mt][nt][3]);
        }
    }
}

// ---------------------------------------------------------------------------
// Kernel 2: per-neuron Izhikevich scan (R3-exact)
// ---------------------------------------------------------------------------
struct NeuronP { float TS, V2, V1, V0, KA, Bp, TH, Cc, D; };

__device__ __forceinline__ void snn_step(float Ic, int t, int g,
                                         const NeuronP& P, float& u, float& v,
                                         float* __restrict__ out)
{
    float t0 = P.V0 - u + Ic;
    t0 = fmaf(P.V1, v, t0);
    t0 = fmaf(P.V2, v * v, t0);
    const float vn = fmaf(P.TS, t0, v);
    const float un = fmaf(P.KA, fmaf(P.Bp, v, -u), u);
    const bool  sp = (vn - P.TH) > 0.f;
    const float s  = sp ? 1.f : 0.f;
    const float vo = sp ? P.Cc : vn;
    const float uo = sp ? (un + P.D) : un;

    out[(size_t)t * PLANE + g] = s;
    const size_t sb = STATES_OFF + (size_t)t * (3 * PLANE) + g;
    out[sb]             = uo;
    out[sb + PLANE]     = vo;
    out[sb + 2 * PLANE] = s;
    u = uo; v = vo;
}

__global__ __launch_bounds__(128) void scan_kernel(
    const float* __restrict__ st,
    const float* __restrict__ pa,  const float* __restrict__ pb,
    const float* __restrict__ pc,  const float* __restrict__ pd,
    const float* __restrict__ pv2, const float* __restrict__ pv1,
    const float* __restrict__ pv0, const float* __restrict__ ptau,
    const float* __restrict__ pth, const float* __restrict__ pts,
    float* __restrict__ out)
{
    const int g = blockIdx.x * 128 + threadIdx.x;
    const int n = g & (NDIM - 1);

    NeuronP P;
    P.TS = pts[n];
    P.V2 = pv2[n]; P.V1 = pv1[n]; P.V0 = pv0[n];
    P.KA = P.TS / ptau[n] * pa[n];
    P.Bp = pb[n]; P.TH = pth[n]; P.Cc = pc[n]; P.D = pd[n];

    float u = st[g];
    float v = st[PLANE + g];

    const float* Ip = g_I + (size_t)(g >> 9) * ((size_t)T_STEPS * NDIM) + n;

    float bufA[8], bufB[8];
    #pragma unroll
    for (int p = 0; p < 8; p++) bufA[p] = Ip[(size_t)p * NDIM];

    #pragma unroll 1
    for (int t0 = 0; t0 < 992; t0 += 16) {
        #pragma unroll
        for (int p = 0; p < 8; p++) bufB[p] = Ip[(size_t)(t0 + 8 + p) * NDIM];
        #pragma unroll
        for (int p = 0; p < 8; p++) snn_step(bufA[p], t0 + p, g, P, u, v, out);
        #pragma unroll
        for (int p = 0; p < 8; p++) bufA[p] = Ip[(size_t)(t0 + 16 + p) * NDIM];
        #pragma unroll
        for (int p = 0; p < 8; p++) snn_step(bufB[p], t0 + 8 + p, g, P, u, v, out);
    }
    #pragma unroll
    for (int p = 0; p < 8; p++) snn_step(bufA[p], 992 + p, g, P, u, v, out);
}

// ---------------------------------------------------------------------------
// Kernel 3: r[t*B+b] = sum_n s[t,b,n] * W2[n]   (R3-exact)
// ---------------------------------------------------------------------------
__global__ __launch_bounds__(128) void readout_reduce_kernel(
    const float* __restrict__ out, const float* __restrict__ W2)
{
    const int tb = blockIdx.x;
    const float* sp = out + (size_t)tb * NDIM;
    const int tid = threadIdx.x;

    float sum = 0.f;
    #pragma unroll
    for (int j = 0; j < 4; j++) {
        const int n = tid + j * 128;
        sum = fmaf(sp[n], W2[n], sum);
    }
    #pragma unroll
    for (int o = 16; o > 0; o >>= 1)
        sum += __shfl_xor_sync(0xffffffffu, sum, o);

    __shared__ float ws[4];
    if ((tid & 31) == 0) ws[tid >> 5] = sum;
    __syncthreads();
    if (tid == 0) g_r[tb] = (ws[0] + ws[1]) + (ws[2] + ws[3]);
}

// ---------------------------------------------------------------------------
// Kernel 4: li recurrence — warp-parallel linear-recurrence scan (R3-exact)
// ---------------------------------------------------------------------------
__global__ void li_kernel(const float* __restrict__ stLI,
                          const float* __restrict__ leak,
                          float* __restrict__ out)
{
    const int b = blockIdx.x;
    const int lane = threadIdx.x;    // 32 threads
    const float lk = leak[0];
    const float l1 = lk, l2 = l1 * l1, l4 = l2 * l2, l8 = l4 * l4, l16 = l8 * l8;
    float lpow = lk;                 // leak^(lane+1)
    {
        float sq[5] = {l1, l2, l4, l8, l16};
        #pragma unroll
        for (int i = 0; i < 5; i++)
            if ((lane >> i) & 1) lpow *= sq[i];
    }

    float carry = stLI[b];
    float x = g_r[lane * BATCH + b];

    #pragma unroll 1
    for (int t0 = 0; t0 < T_STEPS; t0 += 32) {
        const int tn = t0 + 32 + lane;
        const float xn = (tn < T_STEPS) ? g_r[tn * BATCH + b] : 0.f;

        float y = x, up;
        up = __shfl_up_sync(0xffffffffu, y, 1);  if (lane >= 1)  y = fmaf(l1,  up, y);
        up = __shfl_up_sync(0xffffffffu, y, 2);  if (lane >= 2)  y = fmaf(l2,  up, y);
        up = __shfl_up_sync(0xffffffffu, y, 4);  if (lane >= 4)  y = fmaf(l4,  up, y);
        up = __shfl_up_sync(0xffffffffu, y, 8);  if (lane >= 8)  y = fmaf(l8,  up, y);
        up = __shfl_up_sync(0xffffffffu, y, 16); if (lane >= 16) y = fmaf(l16, up, y);

        const float li = fmaf(lpow, carry, y);
        if (t0 + lane < T_STEPS)
            out[DEC_OFF + (size_t)(t0 + lane) * BATCH + b] = li;
        carry = __shfl_sync(0xffffffffu, li, 31);
        x = xn;
    }
}

// ---------------------------------------------------------------------------
extern "C" void kernel_launch(void* const* d_in, const int* in_sizes, int n_in,
                              void* d_out, int out_size)
{
    const float* x    = (const float*)d_in[0];
    const float* st   = (const float*)d_in[1];
    const float* stLI = (const float*)d_in[2];
    const float* W1   = (const float*)d_in[3];
    const float* W2   = (const float*)d_in[4];
    const float* a_   = (const float*)d_in[5];
    const float* b_   = (const float*)d_in[6];
    const float* c_   = (const float*)d_in[7];
    const float* d_   = (const float*)d_in[8];
    const float* v2_  = (const float*)d_in[9];
    const float* v1_  = (const float*)d_in[10];
    const float* v0_  = (const float*)d_in[11];
    const float* tau_ = (const float*)d_in[12];
    const float* th_  = (const float*)d_in[13];
    const float* lk_  = (const float*)d_in[14];
    const float* ts_  = (const float*)d_in[15];
    float* out = (float*)d_out;

    const int smem_bytes = 2 * STAGEW * (int)sizeof(uint32_t);   // 73728
    cudaFuncSetAttribute(gemm_f16pair_kernel,
                         cudaFuncAttributeMaxDynamicSharedMemorySize, smem_bytes);

    dim3 ggrid(MROWS / 128, NDIM / 128);   // (500, 4) — R3 grid order
    gemm_f16pair_kernel<<<ggrid, 256, smem_bytes>>>(x, W1);
    scan_kernel<<<(BATCH * NDIM) / 128, 128>>>(st, a_, b_, c_, d_, v2_, v1_,
                                               v0_, tau_, th_, ts_, out);
    readout_reduce_kernel<<<T_STEPS * BATCH, 128>>>(out, W2);
    li_kernel<<<BATCH, 32>>>(stLI, lk_, out);
}

// round 7
// speedup vs baseline: 1.5774x; 1.0496x over previous
#include <cuda_runtime.h>
#include <cuda_fp16.h>
#include <cstdint>
#include <cstddef>
#include <cmath>

// Problem constants
#define T_STEPS 1000
#define BATCH   64
#define NDIM    512
#define KDIM    512
#define MROWS   (BATCH * T_STEPS)   // 64000

static constexpr size_t PLANE      = (size_t)BATCH * NDIM;          // 32768
static constexpr size_t STATES_OFF = (size_t)T_STEPS * PLANE;       // outputs plane elems
static constexpr size_t DEC_OFF    = STATES_OFF + 3 * STATES_OFF;   // after states [T,3,B,N]

// Scratch
__device__ __align__(16) float g_I[(size_t)MROWS * NDIM];
__device__ float g_r[T_STEPS * BATCH];

// ---------------------------------------------------------------------------
// fp16 Dekker-pair helpers: x -> half2(hi=rn16(x), lo=rn16(x-hi)), interleaved
// along mma-k. pass1 (A_il x B_il) = hi*hi + lo*lo; pass2 (A_il x swap16(B_il))
// = hi*lo + lo*hi. Sum = full product, ~2^-22 relative error.
// ---------------------------------------------------------------------------
__device__ __forceinline__ uint32_t pack_hilo(float x) {
    __half h = __float2half_rn(x);
    float r = x - __half2float(h);
    __half2 p = __halves2half2(h, __float2half_rn(r));
    return *reinterpret_cast<uint32_t*>(&p);
}

__device__ __forceinline__ void mma_f16(float* c, const uint32_t* a, const uint32_t* b) {
    asm volatile(
        "mma.sync.aligned.m16n8k16.row.col.f32.f16.f16.f32 "
        "{%0,%1,%2,%3}, {%4,%5,%6,%7}, {%8,%9}, {%0,%1,%2,%3};\n"
        : "+f"(c[0]), "+f"(c[1]), "+f"(c[2]), "+f"(c[3])
        : "r"(a[0]), "r"(a[1]), "r"(a[2]), "r"(a[3]), "r"(b[0]), "r"(b[1]));
}

// ---------------------------------------------------------------------------
// Kernel 1: I = X @ W1^T  (NT GEMM), fp16 Dekker-pair mma, 2 passes.
// R7: 512 threads (16 warps, 4x4 grid), warp tile 32x32 -> 4 warps/SMSP for
// latency hiding; pass-separated mma ordering (no same-acc back-to-back).
// smem: stride-36-word rows (4*lq+lr covers all banks), 2 stages, 72KB.
// ---------------------------------------------------------------------------
#define BKR    32
#define NCHUNK (KDIM / BKR)        // 16
#define WSTR   36                  // uint32 words per row (32 data + 4 pad)
#define TILEW  (128 * WSTR)        // words per tile
#define STAGEW (2 * TILEW)         // words per stage (A + B)

struct LdgRegs { float4 a[2]; float4 b[2]; };   // 8 floats of A + 8 of B

__device__ __forceinline__ void ldg_chunk(LdgRegs& r, const float* __restrict__ xptr,
                                          const float* __restrict__ wptr, int ck)
{
    const float4* xa = (const float4*)(xptr + ck * BKR);
    const float4* wa = (const float4*)(wptr + ck * BKR);
    r.a[0] = xa[0]; r.a[1] = xa[1];
    r.b[0] = wa[0]; r.b[1] = wa[1];
}

__device__ __forceinline__ void sts_chunk(uint32_t* stage, const LdgRegs& r, int row, int kb)
{
    uint32_t* sA = stage + row * WSTR + kb;
    uint32_t* sB = sA + TILEW;
    const float* fa = (const float*)r.a;
    const float* fb = (const float*)r.b;
    #pragma unroll
    for (int j = 0; j < 2; j++) {
        uint4 w;
        w.x = pack_hilo(fa[j * 4 + 0]); w.y = pack_hilo(fa[j * 4 + 1]);
        w.z = pack_hilo(fa[j * 4 + 2]); w.w = pack_hilo(fa[j * 4 + 3]);
        ((uint4*)sA)[j] = w;
    }
    #pragma unroll
    for (int j = 0; j < 2; j++) {
        uint4 w;
        w.x = pack_hilo(fb[j * 4 + 0]); w.y = pack_hilo(fb[j * 4 + 1]);
        w.z = pack_hilo(fb[j * 4 + 2]); w.w = pack_hilo(fb[j * 4 + 3]);
        ((uint4*)sB)[j] = w;
    }
}

__device__ __forceinline__ void compute_chunk(const uint32_t* __restrict__ stage,
                                              float (&acc)[2][4][4],
                                              int wm, int wn, int lane)
{
    const uint32_t* sA = stage;
    const uint32_t* sB = stage + TILEW;
    const int lq = lane >> 2;        // 0..7
    const int lr = lane & 3;         // 0..3

    // 4 k16-slices per chunk; each slice = 8 real k (16 interleaved k')
    #pragma unroll
    for (int s = 0; s < 4; s++) {
        const int c0 = s * 8 + lr;
        uint32_t A[2][4];
        #pragma unroll
        for (int mt = 0; mt < 2; mt++) {
            const int r0 = wm * 32 + mt * 16 + lq;
            A[mt][0] = sA[r0 * WSTR + c0];
            A[mt][1] = sA[(r0 + 8) * WSTR + c0];
            A[mt][2] = sA[r0 * WSTR + c0 + 4];
            A[mt][3] = sA[(r0 + 8) * WSTR + c0 + 4];
        }
        uint32_t B[4][2];
        #pragma unroll
        for (int nt = 0; nt < 4; nt++) {
            const int nr = wn * 32 + nt * 8 + lq;
            B[nt][0] = sB[nr * WSTR + c0];
            B[nt][1] = sB[nr * WSTR + c0 + 4];
        }
        // pass 1: hi*hi + lo*lo — 8 mma, all distinct accumulators
        #pragma unroll
        for (int mt = 0; mt < 2; mt++)
            #pragma unroll
            for (int nt = 0; nt < 4; nt++)
                mma_f16(acc[mt][nt], A[mt], B[nt]);
        // pass 2: hi*lo + lo*hi — swap B halves (alu pipe), distinct accs again
        #pragma unroll
        for (int nt = 0; nt < 4; nt++) {
            uint32_t bs[2];
            bs[0] = __byte_perm(B[nt][0], 0, 0x1032);
            bs[1] = __byte_perm(B[nt][1], 0, 0x1032);
            #pragma unroll
            for (int mt = 0; mt < 2; mt++)
                mma_f16(acc[mt][nt], A[mt], bs);
        }
    }
}

__global__ __launch_bounds__(512, 1) void gemm_f16pair_kernel(const float* __restrict__ X,
                                                              const float* __restrict__ W)
{
    extern __shared__ uint32_t smemw[];      // 2 stages * 9216 words = 72KB
    const int tid  = threadIdx.x;
    const int wid  = tid >> 5;
    const int lane = tid & 31;
    const int wm   = wid & 3;                // 0..3 (M)
    const int wn   = wid >> 2;               // 0..3 (N)
    const int bm   = blockIdx.x * 128;       // R3 grid order
    const int bn   = blockIdx.y * 128;

    // loader mapping: row = tid>>2 (0..127), kb = (tid&3)*8 real-k offset
    const int lrow = tid >> 2;
    const int lkb  = (tid & 3) * 8;
    const float* xptr = X + (size_t)(bm + lrow) * KDIM + lkb;
    const float* wptr = W + (size_t)(bn + lrow) * KDIM + lkb;

    float acc[2][4][4];
    #pragma unroll
    for (int mt = 0; mt < 2; mt++)
        #pragma unroll
        for (int nt = 0; nt < 4; nt++)
            #pragma unroll
            for (int j = 0; j < 4; j++) acc[mt][nt][j] = 0.f;

    {
        LdgRegs r0;
        ldg_chunk(r0, xptr, wptr, 0);
        sts_chunk(smemw, r0, lrow, lkb);
    }
    __syncthreads();

    #pragma unroll 1
    for (int ck = 0; ck < NCHUNK; ck++) {
        const int cur = ck & 1;
        LdgRegs nr;
        if (ck < NCHUNK - 1) ldg_chunk(nr, xptr, wptr, ck + 1);   // LDGs in flight
        compute_chunk(smemw + cur * STAGEW, acc, wm, wn, lane);   // overlap with LDG
        if (ck < NCHUNK - 1) sts_chunk(smemw + (cur ^ 1) * STAGEW, nr, lrow, lkb);
        __syncthreads();
    }

    // Epilogue: direct float2 stores to g_I
    #pragma unroll
    for (int mt = 0; mt < 2; mt++) {
        const int r0 = bm + wm * 32 + mt * 16 + (lane >> 2);
        #pragma unroll
        for (int nt = 0; nt < 4; nt++) {
            const int c = bn + wn * 32 + nt * 8 + 2 * (lane & 3);
            *(float2*)(g_I + (size_t)r0 * NDIM + c)       = make_float2(acc[mt][nt][0], acc[mt][nt][1]);
            *(float2*)(g_I + (size_t)(r0 + 8) * NDIM + c) = make_float2(acc[mt][nt][2], acc[mt][nt][3]);
        }
    }
}

// ---------------------------------------------------------------------------
// Kernel 2: per-neuron Izhikevich scan (R3/R6-exact)
// ---------------------------------------------------------------------------
struct NeuronP { float TS, V2, V1, V0, KA, Bp, TH, Cc, D; };

__device__ __forceinline__ void snn_step(float Ic, int t, int g,
                                         const NeuronP& P, float& u, float& v,
                                         float* __restrict__ out)
{
    float t0 = P.V0 - u + Ic;
    t0 = fmaf(P.V1, v, t0);
    t0 = fmaf(P.V2, v * v, t0);
    const float vn = fmaf(P.TS, t0, v);
    const float un = fmaf(P.KA, fmaf(P.Bp, v, -u), u);
    const bool  sp = (vn - P.TH) > 0.f;
    const float s  = sp ? 1.f : 0.f;
    const float vo = sp ? P.Cc : vn;
    const float uo = sp ? (un + P.D) : un;

    out[(size_t)t * PLANE + g] = s;
    const size_t sb = STATES_OFF + (size_t)t * (3 * PLANE) + g;
    out[sb]             = uo;
    out[sb + PLANE]     = vo;
    out[sb + 2 * PLANE] = s;
    u = uo; v = vo;
}

__global__ __launch_bounds__(128) void scan_kernel(
    const float* __restrict__ st,
    const float* __restrict__ pa,  const float* __restrict__ pb,
    const float* __restrict__ pc,  const float* __restrict__ pd,
    const float* __restrict__ pv2, const float* __restrict__ pv1,
    const float* __restrict__ pv0, const float* __restrict__ ptau,
    const float* __restrict__ pth, const float* __restrict__ pts,
    float* __restrict__ out)
{
    const int g = blockIdx.x * 128 + threadIdx.x;
    const int n = g & (NDIM - 1);

    NeuronP P;
    P.TS = pts[n];
    P.V2 = pv2[n]; P.V1 = pv1[n]; P.V0 = pv0[n];
    P.KA = P.TS / ptau[n] * pa[n];
    P.Bp = pb[n]; P.TH = pth[n]; P.Cc = pc[n]; P.D = pd[n];

    float u = st[g];
    float v = st[PLANE + g];

    const float* Ip = g_I + (size_t)(g >> 9) * ((size_t)T_STEPS * NDIM) + n;

    float bufA[8], bufB[8];
    #pragma unroll
    for (int p = 0; p < 8; p++) bufA[p] = Ip[(size_t)p * NDIM];

    #pragma unroll 1
    for (int t0 = 0; t0 < 992; t0 += 16) {
        #pragma unroll
        for (int p = 0; p < 8; p++) bufB[p] = Ip[(size_t)(t0 + 8 + p) * NDIM];
        #pragma unroll
        for (int p = 0; p < 8; p++) snn_step(bufA[p], t0 + p, g, P, u, v, out);
        #pragma unroll
        for (int p = 0; p < 8; p++) bufA[p] = Ip[(size_t)(t0 + 16 + p) * NDIM];
        #pragma unroll
        for (int p = 0; p < 8; p++) snn_step(bufB[p], t0 + 8 + p, g, P, u, v, out);
    }
    #pragma unroll
    for (int p = 0; p < 8; p++) snn_step(bufA[p], 992 + p, g, P, u, v, out);
}

// ---------------------------------------------------------------------------
// Kernel 3: r[t*B+b] = sum_n s[t,b,n] * W2[n]   (R3-exact)
// ---------------------------------------------------------------------------
__global__ __launch_bounds__(128) void readout_reduce_kernel(
    const float* __restrict__ out, const float* __restrict__ W2)
{
    const int tb = blockIdx.x;
    const float* sp = out + (size_t)tb * NDIM;
    const int tid = threadIdx.x;

    float sum = 0.f;
    #pragma unroll
    for (int j = 0; j < 4; j++) {
        const int n = tid + j * 128;
        sum = fmaf(sp[n], W2[n], sum);
    }
    #pragma unroll
    for (int o = 16; o > 0; o >>= 1)
        sum += __shfl_xor_sync(0xffffffffu, sum, o);

    __shared__ float ws[4];
    if ((tid & 31) == 0) ws[tid >> 5] = sum;
    __syncthreads();
    if (tid == 0) g_r[tb] = (ws[0] + ws[1]) + (ws[2] + ws[3]);
}

// ---------------------------------------------------------------------------
// Kernel 4: li recurrence — warp-parallel linear-recurrence scan (R3-exact)
// ---------------------------------------------------------------------------
__global__ void li_kernel(const float* __restrict__ stLI,
                          const float* __restrict__ leak,
                          float* __restrict__ out)
{
    const int b = blockIdx.x;
    const int lane = threadIdx.x;    // 32 threads
    const float lk = leak[0];
    const float l1 = lk, l2 = l1 * l1, l4 = l2 * l2, l8 = l4 * l4, l16 = l8 * l8;
    float lpow = lk;                 // leak^(lane+1)
    {
        float sq[5] = {l1, l2, l4, l8, l16};
        #pragma unroll
        for (int i = 0; i < 5; i++)
            if ((lane >> i) & 1) lpow *= sq[i];
    }

    float carry = stLI[b];
    float x = g_r[lane * BATCH + b];

    #pragma unroll 1
    for (int t0 = 0; t0 < T_STEPS; t0 += 32) {
        const int tn = t0 + 32 + lane;
        const float xn = (tn < T_STEPS) ? g_r[tn * BATCH + b] : 0.f;

        float y = x, up;
        up = __shfl_up_sync(0xffffffffu, y, 1);  if (lane >= 1)  y = fmaf(l1,  up, y);
        up = __shfl_up_sync(0xffffffffu, y, 2);  if (lane >= 2)  y = fmaf(l2,  up, y);
        up = __shfl_up_sync(0xffffffffu, y, 4);  if (lane >= 4)  y = fmaf(l4,  up, y);
        up = __shfl_up_sync(0xffffffffu, y, 8);  if (lane >= 8)  y = fmaf(l8,  up, y);
        up = __shfl_up_sync(0xffffffffu, y, 16); if (lane >= 16) y = fmaf(l16, up, y);

        const float li = fmaf(lpow, carry, y);
        if (t0 + lane < T_STEPS)
            out[DEC_OFF + (size_t)(t0 + lane) * BATCH + b] = li;
        carry = __shfl_sync(0xffffffffu, li, 31);
        x = xn;
    }
}

// ---------------------------------------------------------------------------
extern "C" void kernel_launch(void* const* d_in, const int* in_sizes, int n_in,
                              void* d_out, int out_size)
{
    const float* x    = (const float*)d_in[0];
    const float* st   = (const float*)d_in[1];
    const float* stLI = (const float*)d_in[2];
    const float* W1   = (const float*)d_in[3];
    const float* W2   = (const float*)d_in[4];
    const float* a_   = (const float*)d_in[5];
    const float* b_   = (const float*)d_in[6];
    const float* c_   = (const float*)d_in[7];
    const float* d_   = (const float*)d_in[8];
    const float* v2_  = (const float*)d_in[9];
    const float* v1_  = (const float*)d_in[10];
    const float* v0_  = (const float*)d_in[11];
    const float* tau_ = (const float*)d_in[12];
    const float* th_  = (const float*)d_in[13];
    const float* lk_  = (const float*)d_in[14];
    const float* ts_  = (const float*)d_in[15];
    float* out = (float*)d_out;

    const int smem_bytes = 2 * STAGEW * (int)sizeof(uint32_t);   // 73728
    cudaFuncSetAttribute(gemm_f16pair_kernel,
                         cudaFuncAttributeMaxDynamicSharedMemorySize, smem_bytes);

    dim3 ggrid(MROWS / 128, NDIM / 128);   // (500, 4) — R3 grid order
    gemm_f16pair_kernel<<<ggrid, 512, smem_bytes>>>(x, W1);
    scan_kernel<<<(BATCH * NDIM) / 128, 128>>>(st, a_, b_, c_, d_, v2_, v1_,
                                               v0_, tau_, th_, ts_, out);
    readout_reduce_kernel<<<T_STEPS * BATCH, 128>>>(out, W2);
    li_kernel<<<BATCH, 32>>>(stLI, lk_, out);
}